// round 2
// baseline (speedup 1.0000x reference)
#include <cuda_runtime.h>
#include <math.h>

#define BB   128
#define NN   512
#define FIN  5
#define HH   64
#define KNN  16
#define COUT 10
#define NODES (BB*NN)
#define HT_STRIDE 528   // 528*4 bytes = 2112, 16B aligned rows, avoids worst bank conflicts

// ---------------- scratch (device globals: no allocation allowed) ----------------
__device__ float g_h0[NODES*HH];
__device__ float g_h1[NODES*HH];
__device__ float g_A [NODES*HH];
__device__ float g_U [NODES*HH];
__device__ int   g_knn[NODES*KNN];

__device__ __forceinline__ float elu1(float x) { return x > 0.f ? x : expm1f(x); }

// ---------------- generic per-node GEMV + ELU:  out[n,:] = elu(in[n,:] @ W + b) ----------------
template<int IN>
__global__ __launch_bounds__(256) void k_lin(const float* __restrict__ in,
                                             const float* __restrict__ W,
                                             const float* __restrict__ b,
                                             float* __restrict__ out)
{
    __shared__ float sW[IN*HH];
    __shared__ float sb[HH];
    int tid = threadIdx.x;
    for (int i = tid; i < IN*HH; i += 256) sW[i] = W[i];
    if (tid < HH) sb[tid] = b[tid];
    __syncthreads();

    int node = blockIdx.x * 256 + tid;
    float v[IN];
#pragma unroll
    for (int d = 0; d < IN; d++) v[d] = in[node*IN + d];

    for (int o = 0; o < HH; o++) {
        float a = sb[o];
#pragma unroll
        for (int d = 0; d < IN; d++) a += v[d] * sW[d*HH + o];
        out[node*HH + o] = elu1(a);
    }
}

// ---------------- EdgeConv layer-0 factorization:
//   U[n]     = h[n] @ W0b                 (W0 rows 64..127)
//   Aself[n] = h[n] @ (W0a - W0b) + b0    (W0 rows 0..63 minus rows 64..127)
__global__ __launch_bounds__(256) void k_pre(const float* __restrict__ h,
                                             const float* __restrict__ W0,
                                             const float* __restrict__ b0,
                                             float* __restrict__ A,
                                             float* __restrict__ U)
{
    __shared__ float sWb[HH*HH];
    __shared__ float sWd[HH*HH];
    __shared__ float sb[HH];
    int tid = threadIdx.x;
    for (int i = tid; i < HH*HH; i += 256) {
        float wa = W0[i];            // row d (xi part)
        float wb = W0[HH*HH + i];    // row 64+d (xj-xi part)
        sWb[i] = wb;
        sWd[i] = wa - wb;
    }
    if (tid < HH) sb[tid] = b0[tid];
    __syncthreads();

    int node = blockIdx.x * 256 + tid;
    float hv[HH];
#pragma unroll
    for (int d = 0; d < HH; d++) hv[d] = h[node*HH + d];

    for (int o = 0; o < HH; o++) {
        float au = 0.f, ad = sb[o];
#pragma unroll
        for (int d = 0; d < HH; d++) {
            au += hv[d] * sWb[d*HH + o];
            ad += hv[d] * sWd[d*HH + o];
        }
        U[node*HH + o] = au;
        A[node*HH + o] = ad;
    }
}

// ---------------- kNN: per batch, 512x512 distance matrix + top-16 smallest (self excluded)
// grid (B, 2), 256 threads. Transposed feature tile in dynamic smem, broadcast float4 reads.
__global__ __launch_bounds__(256) void k_knn(const float* __restrict__ h,
                                             int* __restrict__ knn_out)
{
    extern __shared__ float sm[];
    float* hT = sm;                    // [64][HT_STRIDE]
    float* sq = sm + HH*HT_STRIDE;     // [512]
    int b = blockIdx.x;
    int tid = threadIdx.x;
    const float* hb = h + (size_t)b * NN * HH;

    for (int idx = tid; idx < NN*HH; idx += 256) {
        int n = idx >> 6, d = idx & 63;
        hT[d*HT_STRIDE + n] = hb[idx];
    }
    __syncthreads();
    for (int i = tid; i < NN; i += 256) {
        float s = 0.f;
#pragma unroll
        for (int d = 0; d < HH; d++) { float v = hT[d*HT_STRIDE + i]; s += v*v; }
        sq[i] = s;
    }
    __syncthreads();

    int i = blockIdx.y * 256 + tid;    // my row
    float xi[HH];
#pragma unroll
    for (int d = 0; d < HH; d++) xi[d] = hT[d*HT_STRIDE + i];
    float sqi = sq[i];

    float bd[KNN]; int bi[KNN];
#pragma unroll
    for (int t = 0; t < KNN; t++) { bd[t] = 3.0e38f; bi[t] = 0; }

    for (int jb = 0; jb < NN; jb += 4) {
        float a0 = 0.f, a1 = 0.f, a2 = 0.f, a3 = 0.f;
#pragma unroll
        for (int d = 0; d < HH; d++) {
            float4 hj = *(const float4*)(hT + d*HT_STRIDE + jb);  // broadcast to whole warp
            float xd = xi[d];
            a0 += xd*hj.x; a1 += xd*hj.y; a2 += xd*hj.z; a3 += xd*hj.w;
        }
        float dist[4];
        dist[0] = sqi + sq[jb+0] - 2.f*a0;
        dist[1] = sqi + sq[jb+1] - 2.f*a1;
        dist[2] = sqi + sq[jb+2] - 2.f*a2;
        dist[3] = sqi + sq[jb+3] - 2.f*a3;
#pragma unroll
        for (int t = 0; t < 4; t++) {
            int j = jb + t;
            float dv = dist[t];
            if (j == i) dv = 1e30f;                 // self-loop mask (matches reference)
            if (dv < bd[KNN-1]) {
                float v = dv; int vi = j;
#pragma unroll
                for (int t2 = 0; t2 < KNN; t2++) {  // strict '<' keeps lower index on ties
                    if (v < bd[t2]) {
                        float tf = bd[t2]; bd[t2] = v;  v  = tf;
                        int   ti = bi[t2]; bi[t2] = vi; vi = ti;
                    }
                }
            }
        }
    }

    int node = b*NN + i;
#pragma unroll
    for (int t = 0; t < KNN; t++) knn_out[node*KNN + t] = bi[t];
}

// ---------------- EdgeConv per-edge part: e0 = elu(Aself_i + U_j); h_i = sum_k elu(e0_k @ W1 + b1)
// warp per node; 4 nodes per 128-thread block.
__global__ __launch_bounds__(128) void k_edge(const float* __restrict__ A,
                                              const float* __restrict__ U,
                                              const int* __restrict__ kn,
                                              const float* __restrict__ W1,
                                              const float* __restrict__ b1,
                                              float* __restrict__ hout)
{
    __shared__ float sW[HH*HH];
    __shared__ float sb[HH];
    __shared__ float e0s[4][KNN][HH];
    int tid = threadIdx.x;
    for (int i = tid; i < HH*HH; i += 128) sW[i] = W1[i];
    if (tid < HH) sb[tid] = b1[tid];
    __syncthreads();

    int w = tid >> 5, l = tid & 31;
    int node = blockIdx.x * 4 + w;
    int base = node & ~(NN - 1);       // batch start node
    float a0 = A[node*HH + l];
    float a1 = A[node*HH + l + 32];
    const int* kp = kn + node*KNN;

#pragma unroll
    for (int k = 0; k < KNN; k++) {
        int j = kp[k];
        const float* up = U + (size_t)(base + j) * HH;
        e0s[w][k][l]      = elu1(a0 + up[l]);
        e0s[w][k][l + 32] = elu1(a1 + up[l + 32]);
    }
    __syncwarp();

    float v0[KNN], v1[KNN];
#pragma unroll
    for (int k = 0; k < KNN; k++) { v0[k] = 0.f; v1[k] = 0.f; }

    for (int d = 0; d < HH; d++) {
        float w0 = sW[d*HH + l];
        float w1 = sW[d*HH + l + 32];
#pragma unroll
        for (int k = 0; k < KNN; k++) {
            float e = e0s[w][k][d];    // broadcast
            v0[k] += e * w0;
            v1[k] += e * w1;
        }
    }

    float bb0 = sb[l], bb1 = sb[l + 32];
    float o0 = 0.f, o1 = 0.f;
#pragma unroll
    for (int k = 0; k < KNN; k++) { o0 += elu1(v0[k] + bb0); o1 += elu1(v1[k] + bb1); }
    hout[node*HH + l]      = o0;
    hout[node*HH + l + 32] = o1;
}

// ---------------- global max-pool + 3-layer output MLP + log_softmax. block per batch.
__global__ __launch_bounds__(64) void k_out(const float* __restrict__ h,
                                            const float* __restrict__ Wo0, const float* __restrict__ bo0,
                                            const float* __restrict__ Wo1, const float* __restrict__ bo1,
                                            const float* __restrict__ Wo2, const float* __restrict__ bo2,
                                            float* __restrict__ out)
{
    int b = blockIdx.x, o = threadIdx.x;
    __shared__ float s0[HH], s1[HH], slog[COUT + 1];
    const float* hb = h + (size_t)b * NN * HH;

    float m = -3.0e38f;
    for (int n = 0; n < NN; n++) m = fmaxf(m, hb[n*HH + o]);
    s0[o] = m;
    __syncthreads();

    float a = bo0[o];
    for (int d = 0; d < HH; d++) a += s0[d] * Wo0[d*HH + o];
    s1[o] = elu1(a);
    __syncthreads();

    a = bo1[o];
    for (int d = 0; d < HH; d++) a += s1[d] * Wo1[d*HH + o];
    __syncthreads();           // everyone done reading s0 (long ago) & s1; safe to reuse s0
    s0[o] = elu1(a);
    __syncthreads();

    if (o < COUT) {
        float lg = bo2[o];
        for (int d = 0; d < HH; d++) lg += s0[d] * Wo2[d*COUT + o];
        slog[o] = lg;
    }
    __syncthreads();
    if (o == 0) {
        float mx = -3.0e38f;
        for (int c = 0; c < COUT; c++) mx = fmaxf(mx, slog[c]);
        float s = 0.f;
        for (int c = 0; c < COUT; c++) s += expf(slog[c] - mx);
        slog[COUT] = mx + logf(s);
    }
    __syncthreads();
    if (o < COUT) out[b*COUT + o] = slog[o] - slog[COUT];
}

// ---------------- host launcher ----------------
extern "C" void kernel_launch(void* const* d_in, const int* in_sizes, int n_in,
                              void* d_out, int out_size)
{
    const float* x     = (const float*)d_in[0];
    const float* W_in0 = (const float*)d_in[1];
    const float* b_in0 = (const float*)d_in[2];
    const float* W_in1 = (const float*)d_in[3];
    const float* b_in1 = (const float*)d_in[4];
    const float* W_in2 = (const float*)d_in[5];
    const float* b_in2 = (const float*)d_in[6];
    const float* W_e0  = (const float*)d_in[7];   // [2,128,64]
    const float* b_e0  = (const float*)d_in[8];   // [2,64]
    const float* W_e1  = (const float*)d_in[9];   // [2,64,64]
    const float* b_e1  = (const float*)d_in[10];  // [2,64]
    const float* W_o0  = (const float*)d_in[11];
    const float* b_o0  = (const float*)d_in[12];
    const float* W_o1  = (const float*)d_in[13];
    const float* b_o1  = (const float*)d_in[14];
    const float* W_o2  = (const float*)d_in[15];
    const float* b_o2  = (const float*)d_in[16];
    float* out = (float*)d_out;

    float *h0, *h1, *A, *U;
    int* kn;
    cudaGetSymbolAddress((void**)&h0, g_h0);
    cudaGetSymbolAddress((void**)&h1, g_h1);
    cudaGetSymbolAddress((void**)&A,  g_A);
    cudaGetSymbolAddress((void**)&U,  g_U);
    cudaGetSymbolAddress((void**)&kn, g_knn);

    const int knn_smem = (HH*HT_STRIDE + NN) * sizeof(float);
    cudaFuncSetAttribute(k_knn, cudaFuncAttributeMaxDynamicSharedMemorySize, knn_smem);

    // input MLP (3 layers), ping-ponging through scratch: x -> h1 -> A -> h0
    k_lin<FIN><<<NODES/256, 256>>>(x,  W_in0, b_in0, h1);
    k_lin<HH> <<<NODES/256, 256>>>(h1, W_in1, b_in1, A);
    k_lin<HH> <<<NODES/256, 256>>>(A,  W_in2, b_in2, h0);

    // 2 dynamic-kNN EdgeConv layers: h0 -> h1 -> h0
    for (int l = 0; l < 2; l++) {
        const float* hin  = (l == 0) ? h0 : h1;
        float*       hout = (l == 0) ? h1 : h0;
        dim3 kg(BB, 2);
        k_knn<<<kg, 256, knn_smem>>>(hin, kn);
        k_pre<<<NODES/256, 256>>>(hin, W_e0 + (size_t)l*2*HH*HH, b_e0 + l*HH, A, U);
        k_edge<<<NODES/4, 128>>>(A, U, kn, W_e1 + (size_t)l*HH*HH, b_e1 + l*HH, hout);
    }

    // pool + output MLP + log_softmax
    k_out<<<BB, 64>>>(h0, W_o0, b_o0, W_o1, b_o1, W_o2, b_o2, out);
}